// round 15
// baseline (speedup 1.0000x reference)
#include <cuda_runtime.h>

// ----------------------------------------------------------------------------
// ControlWhile persistent kernel, R12.
// R11 (191us): fma=43%, issue=40% -> stall-bound at 16 warps/SM; FFMA2 count
// already at algorithmic minimum. R12 threads the register/occupancy needle:
// TPB=384, __launch_bounds__(384,2) -> 85-reg cap, 2 blocks/SM, 24 warps/SM.
// (R9 proved 64 regs spills; live-set estimate ~70-80 -> 85 should fit.)
// Body identical to R11 to isolate the variable.
// ----------------------------------------------------------------------------

#define CIN    3
#define COUT   16
#define HW     147456            // 384*384
#define NPIX   1179648           // 8*HW
#define NTOT   18874368.0        // NPIX*COUT elements in v
#define THRESH (3.0 * NTOT)      // mean|v| < 3  <=>  sum|v| < 3*NTOT
#define MAX_IT 64
#define MAX_BLOCKS 1024
#define TPB    384

typedef unsigned long long u64;

// Pre-packed weights in the constant bank (one 64-bit const load per FFMA2).
__constant__ u64 k_wpre2[COUT * 2];   // [o*2+{0,1}] = (w0,w1),(w2,0)
__constant__ u64 k_bpre2[COUT];       // (b,0)
__constant__ u64 k_wsh2[COUT * 8];    // [o*8+j] = (w[o][2j], w[o][2j+1])
__constant__ u64 k_bsh2[COUT];        // (b,0)
__constant__ u64 k_wl2[COUT * 8];     // prescaled by 10
__constant__ u64 k_bl2[COUT];         // prescaled by 10, (b,0)

// Staging for the prep kernel (cannot write __constant__ from device code).
__device__ u64 g_pk[COUT * 2 + COUT + COUT * 8 + COUT + COUT * 8 + COUT];

// v, pixel-major packed: g_v[p*8 + j] = f32x2 {chan 2j, chan 2j+1} of pixel p.
__device__ __align__(16) u64 g_v[(size_t)NPIX * 8];
// Per-block |v| partial sums — fully overwritten every phase (replay-safe).
__device__ double g_part[MAX_BLOCKS];
// Grid barrier: count returns to 0; gen monotonic, equality-compared (replay-safe).
__device__ unsigned int g_bar_count;
__device__ volatile unsigned int g_bar_gen;

// ---- packed f32x2 helpers (PTX-only; ptxas won't auto-fuse) ----
__device__ __forceinline__ u64 ffma2(u64 a, u64 b, u64 c) {
    u64 d;
    asm("fma.rn.f32x2 %0, %1, %2, %3;" : "=l"(d) : "l"(a), "l"(b), "l"(c));
    return d;
}
__device__ __forceinline__ u64 pack2(float lo, float hi) {
    u64 d;
    asm("mov.b64 %0, {%1, %2};" : "=l"(d) : "f"(lo), "f"(hi));
    return d;
}
__device__ __forceinline__ float hadd2(u64 v) {
    float lo, hi;
    asm("mov.b64 {%0, %1}, %2;" : "=f"(lo), "=f"(hi) : "l"(v));
    return lo + hi;
}

// HW tanh approximation: 1 MUFU op (~5e-4 max rel err; validated R11 at
// final rel_err 6.7e-6 thanks to contraction through the loop).
__device__ __forceinline__ float tanha(float x) {
    float y;
    asm("tanh.approx.f32 %0, %1;" : "=f"(y) : "f"(x));
    return y;
}

// Software grid barrier (all blocks co-resident; verified at launch).
__device__ __forceinline__ void grid_bar() {
    __syncthreads();
    if (threadIdx.x == 0) {
        __threadfence();
        unsigned g = g_bar_gen;
        unsigned a = atomicAdd(&g_bar_count, 1u);
        if (a == gridDim.x - 1) {
            atomicExch(&g_bar_count, 0u);
            __threadfence();
            g_bar_gen = g + 1;
        } else {
            while (g_bar_gen == g) { __nanosleep(64); }
        }
    }
    __syncthreads();
}

// Block-reduce a float partial into g_part[blockIdx.x] (double).
__device__ __forceinline__ void store_block_partial(float part, double* s_wsum) {
    __syncthreads();
    float v = part;
    #pragma unroll
    for (int o = 16; o > 0; o >>= 1) v += __shfl_xor_sync(0xffffffffu, v, o);
    if ((threadIdx.x & 31) == 0) s_wsum[threadIdx.x >> 5] = (double)v;
    __syncthreads();
    if (threadIdx.x == 0) {
        double s = 0.0;
        #pragma unroll
        for (int i = 0; i < TPB / 32; i++) s += s_wsum[i];
        g_part[blockIdx.x] = s;
    }
}

// ---- prep kernel: pack/prescale weights into staging (then D2D -> constant) --
__global__ void prep_kernel(const float* __restrict__ wpre,
                            const float* __restrict__ bpre,
                            const float* __restrict__ wloop,
                            const float* __restrict__ bloop,
                            const float* __restrict__ wsh,
                            const float* __restrict__ bsh)
{
    int t = threadIdx.x;
    u64* pk_wpre = g_pk;
    u64* pk_bpre = pk_wpre + COUT * 2;
    u64* pk_wsh  = pk_bpre + COUT;
    u64* pk_bsh  = pk_wsh + COUT * 8;
    u64* pk_wl   = pk_bsh + COUT;
    u64* pk_bl   = pk_wl + COUT * 8;

    if (t < COUT * 8) {
        int o = t >> 3, j = t & 7;
        pk_wsh[t] = pack2(wsh[o * COUT + 2 * j], wsh[o * COUT + 2 * j + 1]);
        pk_wl[t]  = pack2(10.0f * wloop[o * COUT + 2 * j],
                          10.0f * wloop[o * COUT + 2 * j + 1]);
    }
    if (t < COUT * 2) {
        int o = t >> 1, j = t & 1;
        pk_wpre[t] = (j == 0) ? pack2(wpre[o * CIN], wpre[o * CIN + 1])
                              : pack2(wpre[o * CIN + 2], 0.0f);
    }
    if (t < COUT) {
        pk_bpre[t] = pack2(bpre[t], 0.0f);
        pk_bsh[t]  = pack2(bsh[t], 0.0f);
        pk_bl[t]   = pack2(10.0f * bloop[t], 0.0f);
    }
}

__global__ void __launch_bounds__(TPB, 2)
control_while_kernel(const float* __restrict__ x, float* __restrict__ out)
{
    __shared__ double s_wsum[TPB / 32];
    __shared__ double s_dec[32];
    __shared__ double s_bcast;

    const int gid    = blockIdx.x * TPB + threadIdx.x;
    const int stride = gridDim.x * TPB;

    // Batch decomposition for planar x/out. stride may exceed any sub-extent:
    // rollover is a while-loop (R3 lesson).
    const int b0i = gid / HW;
    const int i0i = gid - b0i * HW;

    // ---- phase 0: pre conv 3->16 (x planar -> v packed), sum|v| ----
    {
        float part = 0.f;
        int b = b0i, i = i0i;
        for (int q = gid; q < NPIX; q += stride) {
            const float* xp = x + (size_t)b * (CIN * HW) + i;
            u64 xin0 = pack2(xp[0], xp[HW]);
            u64 xin1 = pack2(xp[2 * HW], 0.0f);
            u64 vo[8];
            #pragma unroll
            for (int o = 0; o < COUT; o += 2) {
                u64 a0 = k_bpre2[o];
                u64 a1 = k_bpre2[o + 1];
                a0 = ffma2(k_wpre2[2 * o],     xin0, a0);
                a0 = ffma2(k_wpre2[2 * o + 1], xin1, a0);
                a1 = ffma2(k_wpre2[2 * o + 2], xin0, a1);
                a1 = ffma2(k_wpre2[2 * o + 3], xin1, a1);
                float s0 = hadd2(a0), s1 = hadd2(a1);
                part += fabsf(s0) + fabsf(s1);
                vo[o >> 1] = pack2(s0, s1);
            }
            ulonglong2* vp2 = (ulonglong2*)(g_v + (size_t)q * 8);
            vp2[0] = make_ulonglong2(vo[0], vo[1]);
            vp2[1] = make_ulonglong2(vo[2], vo[3]);
            vp2[2] = make_ulonglong2(vo[4], vo[5]);
            vp2[3] = make_ulonglong2(vo[6], vo[7]);
            i += stride;
            while (i >= HW) { i -= HW; b++; }
        }
        store_block_partial(part, s_wsum);
    }
    grid_bar();

    // ---- data-dependent while loop, fully on-device ----
    for (int it = 0; it < MAX_IT; it++) {
        // decide: 32 threads sum fixed contiguous chunks of g_part, thread 0
        // sums the 32 partials in fixed order -> identical double everywhere.
        {
            int grid = (int)gridDim.x;
            int chunk = (grid + 31) / 32;
            if (threadIdx.x < 32) {
                double s = 0.0;
                int lo = threadIdx.x * chunk;
                int hi = lo + chunk; if (hi > grid) hi = grid;
                for (int i = lo; i < hi; i++)
                    s += ((volatile double*)g_part)[i];
                s_dec[threadIdx.x] = s;
            }
            __syncthreads();
            if (threadIdx.x == 0) {
                double s = 0.0;
                #pragma unroll
                for (int i = 0; i < 32; i++) s += s_dec[i];
                s_bcast = s;
            }
            __syncthreads();
        }
        double tot = s_bcast;
        __syncthreads();
        if (!(tot < THRESH)) break;   // NaN-safe, same as jnp semantics

        float part = 0.f;
        for (int q = gid; q < NPIX; q += stride) {
            u64 vp[8];
            {
                const ulonglong2* p2 = (const ulonglong2*)(g_v + (size_t)q * 8);
                ulonglong2 t0 = p2[0], t1 = p2[1], t2 = p2[2], t3 = p2[3];
                vp[0]=t0.x; vp[1]=t0.y; vp[2]=t1.x; vp[3]=t1.y;
                vp[4]=t2.x; vp[5]=t2.y; vp[6]=t3.x; vp[7]=t3.y;
            }
            // conv w_shared + tanh.approx -> hp (channel-pair packed)
            u64 hp[8];
            #pragma unroll
            for (int o = 0; o < COUT; o += 2) {
                u64 a0 = k_bsh2[o];
                u64 a1 = k_bsh2[o + 1];
                #pragma unroll
                for (int j = 0; j < 8; j++) {
                    a0 = ffma2(k_wsh2[o * 8 + j],       vp[j], a0);
                    a1 = ffma2(k_wsh2[(o + 1) * 8 + j], vp[j], a1);
                }
                hp[o >> 1] = pack2(tanha(hadd2(a0)), tanha(hadd2(a1)));
            }
            // conv w_loop (prescaled by 10), store packed, accumulate |.|
            ulonglong2* vs2 = (ulonglong2*)(g_v + (size_t)q * 8);
            #pragma unroll
            for (int o = 0; o < COUT; o += 4) {
                u64 a0 = k_bl2[o];
                u64 a1 = k_bl2[o + 1];
                u64 a2 = k_bl2[o + 2];
                u64 a3 = k_bl2[o + 3];
                #pragma unroll
                for (int j = 0; j < 8; j++) {
                    a0 = ffma2(k_wl2[o * 8 + j],       hp[j], a0);
                    a1 = ffma2(k_wl2[(o + 1) * 8 + j], hp[j], a1);
                    a2 = ffma2(k_wl2[(o + 2) * 8 + j], hp[j], a2);
                    a3 = ffma2(k_wl2[(o + 3) * 8 + j], hp[j], a3);
                }
                float s0 = hadd2(a0), s1 = hadd2(a1);
                float s2 = hadd2(a2), s3 = hadd2(a3);
                part += fabsf(s0) + fabsf(s1) + fabsf(s2) + fabsf(s3);
                vs2[o >> 2] = make_ulonglong2(pack2(s0, s1), pack2(s2, s3));
            }
        }
        store_block_partial(part, s_wsum);
        grid_bar();
    }

    // ---- final conv w_shared (v packed -> out planar) ----
    {
        int b = b0i, i = i0i;
        for (int q = gid; q < NPIX; q += stride) {
            const ulonglong2* p2 = (const ulonglong2*)(g_v + (size_t)q * 8);
            ulonglong2 t0 = p2[0], t1 = p2[1], t2 = p2[2], t3 = p2[3];
            u64 vp[8] = {t0.x, t0.y, t1.x, t1.y, t2.x, t2.y, t3.x, t3.y};
            float* op = out + (size_t)b * (COUT * HW) + i;
            #pragma unroll
            for (int o = 0; o < COUT; o++) {
                u64 a = k_bsh2[o];
                #pragma unroll
                for (int j = 0; j < 8; j++)
                    a = ffma2(k_wsh2[o * 8 + j], vp[j], a);
                op[(size_t)o * HW] = hadd2(a);
            }
            i += stride;
            while (i >= HW) { i -= HW; b++; }
        }
    }
}

extern "C" void kernel_launch(void* const* d_in, const int* in_sizes, int n_in,
                              void* d_out, int out_size) {
    const float* x     = (const float*)d_in[0];
    const float* wpre  = (const float*)d_in[1];
    const float* bpre  = (const float*)d_in[2];
    const float* wloop = (const float*)d_in[3];
    const float* bloop = (const float*)d_in[4];
    const float* wsh   = (const float*)d_in[5];
    const float* bsh   = (const float*)d_in[6];
    (void)in_sizes; (void)n_in; (void)out_size;

    // 1) pack/prescale weights into staging (device kernel, capture-safe)
    prep_kernel<<<1, 256>>>(wpre, bpre, wloop, bloop, wsh, bsh);

    // 2) D2D async copies staging -> constant bank (graph-capturable)
    void* pk_addr = nullptr;
    cudaGetSymbolAddress(&pk_addr, g_pk);
    const u64* pk = (const u64*)pk_addr;
    size_t off = 0;
    cudaMemcpyToSymbolAsync(k_wpre2, pk + off, COUT * 2 * sizeof(u64), 0,
                            cudaMemcpyDeviceToDevice); off += COUT * 2;
    cudaMemcpyToSymbolAsync(k_bpre2, pk + off, COUT * sizeof(u64), 0,
                            cudaMemcpyDeviceToDevice); off += COUT;
    cudaMemcpyToSymbolAsync(k_wsh2,  pk + off, COUT * 8 * sizeof(u64), 0,
                            cudaMemcpyDeviceToDevice); off += COUT * 8;
    cudaMemcpyToSymbolAsync(k_bsh2,  pk + off, COUT * sizeof(u64), 0,
                            cudaMemcpyDeviceToDevice); off += COUT;
    cudaMemcpyToSymbolAsync(k_wl2,   pk + off, COUT * 8 * sizeof(u64), 0,
                            cudaMemcpyDeviceToDevice); off += COUT * 8;
    cudaMemcpyToSymbolAsync(k_bl2,   pk + off, COUT * sizeof(u64), 0,
                            cudaMemcpyDeviceToDevice);

    int dev = 0;
    cudaGetDevice(&dev);
    int sms = 0;
    cudaDeviceGetAttribute(&sms, cudaDevAttrMultiProcessorCount, dev);
    if (sms < 1) sms = 148;

    // Co-residency verified, not assumed: barrier is deadlock-free iff
    // gridDim <= sms * blocksPerSM. With launch_bounds(384,2) occ should be 2.
    int occ = 0;
    cudaOccupancyMaxActiveBlocksPerMultiprocessor(&occ, control_while_kernel,
                                                  TPB, 0);
    if (occ < 1) occ = 1;
    long long want = (long long)sms * occ;
    int blocks = (want > MAX_BLOCKS) ? MAX_BLOCKS : (int)want;

    control_while_kernel<<<blocks, TPB>>>(x, (float*)d_out);
}

// round 16
// speedup vs baseline: 1.0103x; 1.0103x over previous
#include <cuda_runtime.h>

// ----------------------------------------------------------------------------
// ControlWhile persistent kernel, R13.
// R12 falsified latency-hiding (+50% warps -> issue pinned at 40%, dur flat):
// a per-SMSP THROUGHPUT port is saturated. Prime suspect: LDC floor=8/SMSP
// (~128 LDC.64/pixel ~= measured loop time). R13 halves the constant-port
// instruction count with LDC.128 (weights as ulonglong2, 2 packed weights per
// load) and moves |.| accumulation to packed add.f32x2 (+abs mask), reusing
// the store pack. Config back to R11 (TPB=512, occ 1; R12's 2nd block: nil).
// ----------------------------------------------------------------------------

#define CIN    3
#define COUT   16
#define HW     147456            // 384*384
#define NPIX   1179648           // 8*HW
#define NTOT   18874368.0        // NPIX*COUT elements in v
#define THRESH (3.0 * NTOT)      // mean|v| < 3  <=>  sum|v| < 3*NTOT
#define MAX_IT 64
#define MAX_BLOCKS 1024
#define TPB    512

typedef unsigned long long u64;

// Weights in the constant bank as 16B vectors -> one LDC.128 = 2 packed weights.
// Byte layout identical to R11 staging (u64 pairs contiguous).
__constant__ ulonglong2 k2_wpre[COUT];    // per o: ((w0,w1),(w2,0))
__constant__ u64        k_bpre2[COUT];    // (b,0)
__constant__ ulonglong2 k2_wsh[COUT * 4]; // [o*4+jj] = ((w2j,w2j+1),(w2j+2,w2j+3))
__constant__ u64        k_bsh2[COUT];     // (b,0)
__constant__ ulonglong2 k2_wl[COUT * 4];  // prescaled by 10
__constant__ u64        k_bl2[COUT];      // prescaled by 10, (b,0)

// Staging for the prep kernel (cannot write __constant__ from device code).
__device__ u64 g_pk[COUT * 2 + COUT + COUT * 8 + COUT + COUT * 8 + COUT];

// v, pixel-major packed: g_v[p*8 + j] = f32x2 {chan 2j, chan 2j+1} of pixel p.
__device__ __align__(16) u64 g_v[(size_t)NPIX * 8];
// Per-block |v| partial sums — fully overwritten every phase (replay-safe).
__device__ double g_part[MAX_BLOCKS];
// Grid barrier: count returns to 0; gen monotonic, equality-compared (replay-safe).
__device__ unsigned int g_bar_count;
__device__ volatile unsigned int g_bar_gen;

#define ABS2 0x7FFFFFFF7FFFFFFFull

// ---- packed f32x2 helpers (PTX-only; ptxas won't auto-fuse) ----
__device__ __forceinline__ u64 ffma2(u64 a, u64 b, u64 c) {
    u64 d;
    asm("fma.rn.f32x2 %0, %1, %2, %3;" : "=l"(d) : "l"(a), "l"(b), "l"(c));
    return d;
}
__device__ __forceinline__ u64 add2(u64 a, u64 b) {
    u64 d;
    asm("add.rn.f32x2 %0, %1, %2;" : "=l"(d) : "l"(a), "l"(b));
    return d;
}
__device__ __forceinline__ u64 pack2(float lo, float hi) {
    u64 d;
    asm("mov.b64 %0, {%1, %2};" : "=l"(d) : "f"(lo), "f"(hi));
    return d;
}
__device__ __forceinline__ float hadd2(u64 v) {
    float lo, hi;
    asm("mov.b64 {%0, %1}, %2;" : "=f"(lo), "=f"(hi) : "l"(v));
    return lo + hi;
}

// HW tanh approximation: 1 MUFU op (validated R11: final rel_err 6.7e-6).
__device__ __forceinline__ float tanha(float x) {
    float y;
    asm("tanh.approx.f32 %0, %1;" : "=f"(y) : "f"(x));
    return y;
}

// Software grid barrier (all blocks co-resident; verified at launch).
__device__ __forceinline__ void grid_bar() {
    __syncthreads();
    if (threadIdx.x == 0) {
        __threadfence();
        unsigned g = g_bar_gen;
        unsigned a = atomicAdd(&g_bar_count, 1u);
        if (a == gridDim.x - 1) {
            atomicExch(&g_bar_count, 0u);
            __threadfence();
            g_bar_gen = g + 1;
        } else {
            while (g_bar_gen == g) { __nanosleep(64); }
        }
    }
    __syncthreads();
}

// Block-reduce a float partial into g_part[blockIdx.x] (double).
__device__ __forceinline__ void store_block_partial(float part, double* s_wsum) {
    __syncthreads();
    float v = part;
    #pragma unroll
    for (int o = 16; o > 0; o >>= 1) v += __shfl_xor_sync(0xffffffffu, v, o);
    if ((threadIdx.x & 31) == 0) s_wsum[threadIdx.x >> 5] = (double)v;
    __syncthreads();
    if (threadIdx.x == 0) {
        double s = 0.0;
        #pragma unroll
        for (int i = 0; i < TPB / 32; i++) s += s_wsum[i];
        g_part[blockIdx.x] = s;
    }
}

// ---- prep kernel: pack/prescale weights into staging (then D2D -> constant) --
__global__ void prep_kernel(const float* __restrict__ wpre,
                            const float* __restrict__ bpre,
                            const float* __restrict__ wloop,
                            const float* __restrict__ bloop,
                            const float* __restrict__ wsh,
                            const float* __restrict__ bsh)
{
    int t = threadIdx.x;
    u64* pk_wpre = g_pk;
    u64* pk_bpre = pk_wpre + COUT * 2;
    u64* pk_wsh  = pk_bpre + COUT;
    u64* pk_bsh  = pk_wsh + COUT * 8;
    u64* pk_wl   = pk_bsh + COUT;
    u64* pk_bl   = pk_wl + COUT * 8;

    if (t < COUT * 8) {
        int o = t >> 3, j = t & 7;
        pk_wsh[t] = pack2(wsh[o * COUT + 2 * j], wsh[o * COUT + 2 * j + 1]);
        pk_wl[t]  = pack2(10.0f * wloop[o * COUT + 2 * j],
                          10.0f * wloop[o * COUT + 2 * j + 1]);
    }
    if (t < COUT * 2) {
        int o = t >> 1, j = t & 1;
        pk_wpre[t] = (j == 0) ? pack2(wpre[o * CIN], wpre[o * CIN + 1])
                              : pack2(wpre[o * CIN + 2], 0.0f);
    }
    if (t < COUT) {
        pk_bpre[t] = pack2(bpre[t], 0.0f);
        pk_bsh[t]  = pack2(bsh[t], 0.0f);
        pk_bl[t]   = pack2(10.0f * bloop[t], 0.0f);
    }
}

__global__ void __launch_bounds__(TPB, 1)
control_while_kernel(const float* __restrict__ x, float* __restrict__ out)
{
    __shared__ double s_wsum[TPB / 32];
    __shared__ double s_dec[32];
    __shared__ double s_bcast;

    const int gid    = blockIdx.x * TPB + threadIdx.x;
    const int stride = gridDim.x * TPB;

    // Batch decomposition for planar x/out. stride may exceed any sub-extent:
    // rollover is a while-loop (R3 lesson).
    const int b0i = gid / HW;
    const int i0i = gid - b0i * HW;

    // ---- phase 0: pre conv 3->16 (x planar -> v packed), sum|v| ----
    {
        u64 part2 = 0;
        int b = b0i, i = i0i;
        for (int q = gid; q < NPIX; q += stride) {
            const float* xp = x + (size_t)b * (CIN * HW) + i;
            u64 xin0 = pack2(xp[0], xp[HW]);
            u64 xin1 = pack2(xp[2 * HW], 0.0f);
            u64 vo[8];
            #pragma unroll
            for (int o = 0; o < COUT; o += 2) {
                ulonglong2 w0 = k2_wpre[o];
                ulonglong2 w1 = k2_wpre[o + 1];
                u64 a0 = k_bpre2[o];
                u64 a1 = k_bpre2[o + 1];
                a0 = ffma2(w0.x, xin0, a0);
                a0 = ffma2(w0.y, xin1, a0);
                a1 = ffma2(w1.x, xin0, a1);
                a1 = ffma2(w1.y, xin1, a1);
                u64 p = pack2(hadd2(a0), hadd2(a1));
                part2 = add2(part2, p & ABS2);
                vo[o >> 1] = p;
            }
            ulonglong2* vp2 = (ulonglong2*)(g_v + (size_t)q * 8);
            vp2[0] = make_ulonglong2(vo[0], vo[1]);
            vp2[1] = make_ulonglong2(vo[2], vo[3]);
            vp2[2] = make_ulonglong2(vo[4], vo[5]);
            vp2[3] = make_ulonglong2(vo[6], vo[7]);
            i += stride;
            while (i >= HW) { i -= HW; b++; }
        }
        store_block_partial(hadd2(part2), s_wsum);
    }
    grid_bar();

    // ---- data-dependent while loop, fully on-device ----
    for (int it = 0; it < MAX_IT; it++) {
        // decide: 32 threads sum fixed contiguous chunks of g_part, thread 0
        // sums the 32 partials in fixed order -> identical double everywhere.
        {
            int grid = (int)gridDim.x;
            int chunk = (grid + 31) / 32;
            if (threadIdx.x < 32) {
                double s = 0.0;
                int lo = threadIdx.x * chunk;
                int hi = lo + chunk; if (hi > grid) hi = grid;
                for (int i = lo; i < hi; i++)
                    s += ((volatile double*)g_part)[i];
                s_dec[threadIdx.x] = s;
            }
            __syncthreads();
            if (threadIdx.x == 0) {
                double s = 0.0;
                #pragma unroll
                for (int i = 0; i < 32; i++) s += s_dec[i];
                s_bcast = s;
            }
            __syncthreads();
        }
        double tot = s_bcast;
        __syncthreads();
        if (!(tot < THRESH)) break;   // NaN-safe, same as jnp semantics

        u64 part2 = 0;
        for (int q = gid; q < NPIX; q += stride) {
            u64 vp[8];
            {
                const ulonglong2* p2 = (const ulonglong2*)(g_v + (size_t)q * 8);
                ulonglong2 t0 = p2[0], t1 = p2[1], t2 = p2[2], t3 = p2[3];
                vp[0]=t0.x; vp[1]=t0.y; vp[2]=t1.x; vp[3]=t1.y;
                vp[4]=t2.x; vp[5]=t2.y; vp[6]=t3.x; vp[7]=t3.y;
            }
            // conv w_shared + tanh.approx -> hp; weights via LDC.128
            u64 hp[8];
            #pragma unroll
            for (int o = 0; o < COUT; o += 2) {
                u64 a0 = k_bsh2[o];
                u64 a1 = k_bsh2[o + 1];
                #pragma unroll
                for (int jj = 0; jj < 4; jj++) {
                    ulonglong2 w0 = k2_wsh[o * 4 + jj];
                    ulonglong2 w1 = k2_wsh[(o + 1) * 4 + jj];
                    a0 = ffma2(w0.x, vp[2 * jj],     a0);
                    a0 = ffma2(w0.y, vp[2 * jj + 1], a0);
                    a1 = ffma2(w1.x, vp[2 * jj],     a1);
                    a1 = ffma2(w1.y, vp[2 * jj + 1], a1);
                }
                hp[o >> 1] = pack2(tanha(hadd2(a0)), tanha(hadd2(a1)));
            }
            // conv w_loop (prescaled by 10), store packed, packed-abs accumulate
            ulonglong2* vs2 = (ulonglong2*)(g_v + (size_t)q * 8);
            #pragma unroll
            for (int o = 0; o < COUT; o += 4) {
                u64 a0 = k_bl2[o];
                u64 a1 = k_bl2[o + 1];
                u64 a2 = k_bl2[o + 2];
                u64 a3 = k_bl2[o + 3];
                #pragma unroll
                for (int jj = 0; jj < 4; jj++) {
                    ulonglong2 w0 = k2_wl[o * 4 + jj];
                    ulonglong2 w1 = k2_wl[(o + 1) * 4 + jj];
                    ulonglong2 w2 = k2_wl[(o + 2) * 4 + jj];
                    ulonglong2 w3 = k2_wl[(o + 3) * 4 + jj];
                    u64 v0 = vp[2 * jj], v1 = vp[2 * jj + 1];
                    a0 = ffma2(w0.x, hp[2 * jj], a0);  a0 = ffma2(w0.y, hp[2 * jj + 1], a0);
                    a1 = ffma2(w1.x, hp[2 * jj], a1);  a1 = ffma2(w1.y, hp[2 * jj + 1], a1);
                    a2 = ffma2(w2.x, hp[2 * jj], a2);  a2 = ffma2(w2.y, hp[2 * jj + 1], a2);
                    a3 = ffma2(w3.x, hp[2 * jj], a3);  a3 = ffma2(w3.y, hp[2 * jj + 1], a3);
                    (void)v0; (void)v1;
                }
                u64 p01 = pack2(hadd2(a0), hadd2(a1));
                u64 p23 = pack2(hadd2(a2), hadd2(a3));
                part2 = add2(part2, p01 & ABS2);
                part2 = add2(part2, p23 & ABS2);
                vs2[o >> 2] = make_ulonglong2(p01, p23);
            }
        }
        store_block_partial(hadd2(part2), s_wsum);
        grid_bar();
    }

    // ---- final conv w_shared (v packed -> out planar) ----
    {
        int b = b0i, i = i0i;
        for (int q = gid; q < NPIX; q += stride) {
            const ulonglong2* p2 = (const ulonglong2*)(g_v + (size_t)q * 8);
            ulonglong2 t0 = p2[0], t1 = p2[1], t2 = p2[2], t3 = p2[3];
            u64 vp[8] = {t0.x, t0.y, t1.x, t1.y, t2.x, t2.y, t3.x, t3.y};
            float* op = out + (size_t)b * (COUT * HW) + i;
            #pragma unroll
            for (int o = 0; o < COUT; o++) {
                u64 a = k_bsh2[o];
                #pragma unroll
                for (int jj = 0; jj < 4; jj++) {
                    ulonglong2 w = k2_wsh[o * 4 + jj];
                    a = ffma2(w.x, vp[2 * jj],     a);
                    a = ffma2(w.y, vp[2 * jj + 1], a);
                }
                op[(size_t)o * HW] = hadd2(a);
            }
            i += stride;
            while (i >= HW) { i -= HW; b++; }
        }
    }
}

extern "C" void kernel_launch(void* const* d_in, const int* in_sizes, int n_in,
                              void* d_out, int out_size) {
    const float* x     = (const float*)d_in[0];
    const float* wpre  = (const float*)d_in[1];
    const float* bpre  = (const float*)d_in[2];
    const float* wloop = (const float*)d_in[3];
    const float* bloop = (const float*)d_in[4];
    const float* wsh   = (const float*)d_in[5];
    const float* bsh   = (const float*)d_in[6];
    (void)in_sizes; (void)n_in; (void)out_size;

    // 1) pack/prescale weights into staging (device kernel, capture-safe)
    prep_kernel<<<1, 256>>>(wpre, bpre, wloop, bloop, wsh, bsh);

    // 2) D2D async copies staging -> constant bank (graph-capturable).
    //    Byte layout identical to R11: u64 pairs contiguous == ulonglong2.
    void* pk_addr = nullptr;
    cudaGetSymbolAddress(&pk_addr, g_pk);
    const u64* pk = (const u64*)pk_addr;
    size_t off = 0;
    cudaMemcpyToSymbolAsync(k2_wpre, pk + off, COUT * 2 * sizeof(u64), 0,
                            cudaMemcpyDeviceToDevice); off += COUT * 2;
    cudaMemcpyToSymbolAsync(k_bpre2, pk + off, COUT * sizeof(u64), 0,
                            cudaMemcpyDeviceToDevice); off += COUT;
    cudaMemcpyToSymbolAsync(k2_wsh,  pk + off, COUT * 8 * sizeof(u64), 0,
                            cudaMemcpyDeviceToDevice); off += COUT * 8;
    cudaMemcpyToSymbolAsync(k_bsh2,  pk + off, COUT * sizeof(u64), 0,
                            cudaMemcpyDeviceToDevice); off += COUT;
    cudaMemcpyToSymbolAsync(k2_wl,   pk + off, COUT * 8 * sizeof(u64), 0,
                            cudaMemcpyDeviceToDevice); off += COUT * 8;
    cudaMemcpyToSymbolAsync(k_bl2,   pk + off, COUT * sizeof(u64), 0,
                            cudaMemcpyDeviceToDevice);

    int dev = 0;
    cudaGetDevice(&dev);
    int sms = 0;
    cudaDeviceGetAttribute(&sms, cudaDevAttrMultiProcessorCount, dev);
    if (sms < 1) sms = 148;

    // Co-residency verified, not assumed: barrier is deadlock-free iff
    // gridDim <= sms * blocksPerSM.
    int occ = 0;
    cudaOccupancyMaxActiveBlocksPerMultiprocessor(&occ, control_while_kernel,
                                                  TPB, 0);
    if (occ < 1) occ = 1;
    long long want = (long long)sms * occ;
    int blocks = (want > MAX_BLOCKS) ? MAX_BLOCKS : (int)want;

    control_while_kernel<<<blocks, TPB>>>(x, (float*)d_out);
}